// round 1
// baseline (speedup 1.0000x reference)
#include <cuda_runtime.h>
#include <cuda_bf16.h>
#include <cstddef>

// Problem constants: x[64,512,128] @ Wx[128,1024] + b -> XP; then
// h_t = tanh(xp_t + h_{t-1} @ Wh[1024,1024]), out[64,512,1024] fp32.
#define BB 64
#define TT 512
#define DD 128
#define HH 1024

typedef unsigned long long ull;

// ---------- Blackwell packed fp32x2 helpers (exact fp32, 2x FMA-pipe rate) ----------
__device__ __forceinline__ ull pk2(float lo, float hi) {
    ull r; asm("mov.b64 %0, {%1, %2};" : "=l"(r) : "f"(lo), "f"(hi)); return r;
}
__device__ __forceinline__ float2 upk2(ull v) {
    float lo, hi; asm("mov.b64 {%0, %1}, %2;" : "=f"(lo), "=f"(hi) : "l"(v));
    return make_float2(lo, hi);
}
__device__ __forceinline__ ull ffma2(ull a, ull b, ull c) {
    ull d; asm("fma.rn.f32x2 %0, %1, %2, %3;" : "=l"(d) : "l"(a), "l"(b), "l"(c));
    return d;
}

// =====================================================================
// Kernel 1: XP = x @ Wx + b   (GEMM M=32768, K=128, N=1024) -> d_out
// Tiles: 64x64, BK=64 (2 chunks). 256 threads, 4x4 microtile via f32x2.
// =====================================================================
__global__ __launch_bounds__(256) void xp_gemm(
    const float* __restrict__ x, const float* __restrict__ Wx,
    const float* __restrict__ bias, float* __restrict__ out)
{
    __shared__ float xs[64 * 68];   // [row][k], padded stride 68 (272B = 17 float4)
    __shared__ float ws[64 * 64];   // [k][col]

    const int tid = threadIdx.x;
    const int m0 = blockIdx.x * 64;
    const int n0 = blockIdx.y * 64;
    const int ty = tid >> 4;        // 0..15 -> rows 4*ty..4*ty+3
    const int tx = tid & 15;        // 0..15 -> cols 4*tx..4*tx+3

    ull acc01[4] = {0ull, 0ull, 0ull, 0ull};
    ull acc23[4] = {0ull, 0ull, 0ull, 0ull};

    for (int k0 = 0; k0 < DD; k0 += 64) {
        __syncthreads();
        // load x tile: 64 rows x 64 k  (1024 float4)
        #pragma unroll
        for (int i = tid; i < 1024; i += 256) {
            int r = i >> 4, q = i & 15;
            ((float4*)xs)[r * 17 + q] =
                *(const float4*)&x[(size_t)(m0 + r) * DD + k0 + 4 * q];
        }
        // load Wx tile: 64 k x 64 cols
        #pragma unroll
        for (int i = tid; i < 1024; i += 256) {
            int r = i >> 4, q = i & 15;
            ((float4*)ws)[i] =
                *(const float4*)&Wx[(size_t)(k0 + r) * HH + n0 + 4 * q];
        }
        __syncthreads();

        #pragma unroll 8
        for (int kk = 0; kk < 64; kk++) {
            ulonglong2 wv = *(const ulonglong2*)&ws[kk * 64 + 4 * tx];
            #pragma unroll
            for (int i = 0; i < 4; i++) {
                float a = xs[(4 * ty + i) * 68 + kk];
                ull aa = pk2(a, a);
                acc01[i] = ffma2(aa, wv.x, acc01[i]);
                acc23[i] = ffma2(aa, wv.y, acc23[i]);
            }
        }
    }

    float4 bv = *(const float4*)&bias[n0 + 4 * tx];
    #pragma unroll
    for (int i = 0; i < 4; i++) {
        float2 p0 = upk2(acc01[i]);
        float2 p1 = upk2(acc23[i]);
        float4 r;
        r.x = p0.x + bv.x; r.y = p0.y + bv.y;
        r.z = p1.x + bv.z; r.w = p1.y + bv.w;
        *(float4*)&out[(size_t)(m0 + 4 * ty + i) * HH + n0 + 4 * tx] = r;
    }
}

// =====================================================================
// Kernel 2: one recurrence step.
//   For CTA n-slice (8 cols): z[b, n] = xp[b,t,n] + sum_k h[b,t-1,k]*Wh[k,n]
//   out[b,t,n] = tanh(z)   (in-place over xp)
// Grid 128 CTAs x 128 threads. Wh slice (1024x8 fp32 = 32KB) in SMEM,
// H staged in 4 chunks of 256 k (64x260 padded, 65 float4/row).
// =====================================================================
#define CK 256
#define HSTRIDE 260   /* 256 + pad4; 260*4B = 65*16B -> float4-clean, conflict-light */

__global__ __launch_bounds__(128) void rnn_step(
    float* __restrict__ out, const float* __restrict__ Wh, int t)
{
    extern __shared__ float sm[];
    float* whs = sm;                  // [k][8], 8192 floats
    float* hs  = sm + HH * 8;         // [b][kk], 64 * HSTRIDE floats

    const int tid = threadIdx.x;
    const int n0 = blockIdx.x * 8;
    const int b  = tid >> 1;          // 0..63
    const int cg = tid & 1;           // column group: cols 4*cg..4*cg+3

    ull acc0 = 0ull, acc1 = 0ull;     // (c0,c1), (c2,c3)

    if (t > 0) {
        // Load Wh slice: 1024 rows x 8 cols = 2048 float4
        #pragma unroll
        for (int i = tid; i < 2048; i += 128) {
            int k = i >> 1, q = i & 1;
            ((float4*)whs)[i] = *(const float4*)&Wh[(size_t)k * HH + n0 + 4 * q];
        }

        for (int k0 = 0; k0 < HH; k0 += CK) {
            __syncthreads();
            // Stage h[., t-1, k0:k0+256] : 64 rows x 64 float4
            #pragma unroll
            for (int i = tid; i < 4096; i += 128) {
                int bb = i >> 6, q = i & 63;
                ((float4*)hs)[bb * 65 + q] =
                    *(const float4*)&out[((size_t)bb * TT + (t - 1)) * HH + k0 + 4 * q];
            }
            __syncthreads();

            const float* hrow = &hs[b * HSTRIDE];
            #pragma unroll 4
            for (int kk = 0; kk < CK; kk += 2) {
                float2 hv = *(const float2*)&hrow[kk];
                ull hh0 = pk2(hv.x, hv.x);
                ull hh1 = pk2(hv.y, hv.y);
                ulonglong2 w0 = *(const ulonglong2*)&whs[(k0 + kk) * 8 + 4 * cg];
                ulonglong2 w1 = *(const ulonglong2*)&whs[(k0 + kk + 1) * 8 + 4 * cg];
                acc0 = ffma2(hh0, w0.x, acc0);
                acc1 = ffma2(hh0, w0.y, acc1);
                acc0 = ffma2(hh1, w1.x, acc0);
                acc1 = ffma2(hh1, w1.y, acc1);
            }
        }
    }

    // Epilogue: z = xp + acc; h = tanh(z); write back in place.
    size_t o = ((size_t)b * TT + t) * HH + n0 + 4 * cg;
    float4 xp = *(const float4*)&out[o];
    float2 p0 = upk2(acc0);
    float2 p1 = upk2(acc1);
    float4 r;
    r.x = tanhf(xp.x + p0.x);
    r.y = tanhf(xp.y + p0.y);
    r.z = tanhf(xp.z + p1.x);
    r.w = tanhf(xp.w + p1.y);
    *(float4*)&out[o] = r;
}

// =====================================================================
// Launch
// =====================================================================
extern "C" void kernel_launch(void* const* d_in, const int* in_sizes, int n_in,
                              void* d_out, int out_size)
{
    const float* x  = nullptr;
    const float* Wx = nullptr;
    const float* Wh = nullptr;
    const float* bv = nullptr;
    for (int i = 0; i < n_in; i++) {
        int s = in_sizes[i];
        if (s == BB * TT * DD)      x  = (const float*)d_in[i];
        else if (s == DD * HH)      Wx = (const float*)d_in[i];
        else if (s == HH * HH)      Wh = (const float*)d_in[i];
        else if (s == HH)           bv = (const float*)d_in[i];
    }
    float* out = (float*)d_out;

    const int smem2 = (HH * 8 + 64 * HSTRIDE) * (int)sizeof(float); // 99328 B
    cudaFuncSetAttribute(rnn_step, cudaFuncAttributeMaxDynamicSharedMemorySize, smem2);

    dim3 g1((BB * TT) / 64, HH / 64);   // (512, 16)
    xp_gemm<<<g1, 256>>>(x, Wx, bv, out);

    for (int t = 0; t < TT; t++) {
        rnn_step<<<HH / 8, 128, smem2>>>(out, Wh, t);
    }
}

// round 2
// speedup vs baseline: 1.4337x; 1.4337x over previous
#include <cuda_runtime.h>
#include <cuda_bf16.h>
#include <cstddef>

// x[64,512,128] @ Wx[128,1024] + b -> XP (in d_out); then
// h_t = tanh(xp_t + h_{t-1} @ Wh[1024,1024]); out[b,t,:] = h_t.
#define BB 64
#define TT 512
#define DD 128
#define HH 1024

typedef unsigned long long ull;

// ---------- Blackwell packed fp32x2 helpers (exact fp32, 2x FMA rate) ----------
__device__ __forceinline__ ull pk2(float lo, float hi) {
    ull r; asm("mov.b64 %0, {%1, %2};" : "=l"(r) : "f"(lo), "f"(hi)); return r;
}
__device__ __forceinline__ float2 upk2(ull v) {
    float lo, hi; asm("mov.b64 {%0, %1}, %2;" : "=f"(lo), "=f"(hi) : "l"(v));
    return make_float2(lo, hi);
}
__device__ __forceinline__ ull ffma2(ull a, ull b, ull c) {
    ull d; asm("fma.rn.f32x2 %0, %1, %2, %3;" : "=l"(d) : "l"(a), "l"(b), "l"(c));
    return d;
}

// ---------- global scratch (static: no allocs allowed) ----------
// hT[parity][col k][batch b] : h stored column-major for coalesced per-group reads.
__device__ float g_hT[2][HH][BB];        // 512 KB
__device__ int   g_flags[4 * TT];        // per (batch-group, step) arrival counters

__global__ void reset_flags() {
    int i = blockIdx.x * blockDim.x + threadIdx.x;
    if (i < 4 * TT) g_flags[i] = 0;
}

// =====================================================================
// Kernel 1: XP = x @ Wx + b  -> d_out   (M=32768, K=128, N=1024)
// =====================================================================
__global__ __launch_bounds__(256) void xp_gemm(
    const float* __restrict__ x, const float* __restrict__ Wx,
    const float* __restrict__ bias, float* __restrict__ out)
{
    __shared__ float xs[64 * 68];
    __shared__ float ws[64 * 64];

    const int tid = threadIdx.x;
    const int m0 = blockIdx.x * 64;
    const int n0 = blockIdx.y * 64;
    const int ty = tid >> 4;
    const int tx = tid & 15;

    ull acc01[4] = {0ull, 0ull, 0ull, 0ull};
    ull acc23[4] = {0ull, 0ull, 0ull, 0ull};

    for (int k0 = 0; k0 < DD; k0 += 64) {
        __syncthreads();
        #pragma unroll
        for (int i = tid; i < 1024; i += 256) {
            int r = i >> 4, q = i & 15;
            ((float4*)xs)[r * 17 + q] =
                *(const float4*)&x[(size_t)(m0 + r) * DD + k0 + 4 * q];
        }
        #pragma unroll
        for (int i = tid; i < 1024; i += 256) {
            int r = i >> 4, q = i & 15;
            ((float4*)ws)[i] =
                *(const float4*)&Wx[(size_t)(k0 + r) * HH + n0 + 4 * q];
        }
        __syncthreads();

        #pragma unroll 8
        for (int kk = 0; kk < 64; kk++) {
            ulonglong2 wv = *(const ulonglong2*)&ws[kk * 64 + 4 * tx];
            #pragma unroll
            for (int i = 0; i < 4; i++) {
                float a = xs[(4 * ty + i) * 68 + kk];
                ull aa = pk2(a, a);
                acc01[i] = ffma2(aa, wv.x, acc01[i]);
                acc23[i] = ffma2(aa, wv.y, acc23[i]);
            }
        }
    }

    float4 bv = *(const float4*)&bias[n0 + 4 * tx];
    #pragma unroll
    for (int i = 0; i < 4; i++) {
        float2 p0 = upk2(acc01[i]);
        float2 p1 = upk2(acc23[i]);
        float4 r;
        r.x = p0.x + bv.x; r.y = p0.y + bv.y;
        r.z = p1.x + bv.z; r.w = p1.y + bv.w;
        *(float4*)&out[(size_t)(m0 + 4 * ty + i) * HH + n0 + 4 * tx] = r;
    }
}

// =====================================================================
// Kernel 2: persistent recurrence. 128 CTAs (1/SM), 256 threads.
// CTA (g, j): batches [16g,16g+16), cols [32j,32j+32).
// SMEM: Wh slice [1024][32] resident all steps (128KB);
//       hs [1024][20] staged h (80KB, 16 batches + 4 pad);
//       red [4][16][16] ull k-split partials (8KB).
// Per-group flag sync (32 CTAs per group), h exchanged via g_hT (L2).
// =====================================================================
#define HSROW 20

__global__ __launch_bounds__(256) void rnn_persist(
    float* __restrict__ out, const float* __restrict__ Wh)
{
    extern __shared__ float sm[];
    float* whs = sm;                       // 32768 floats
    float* hs  = sm + 32768;               // 20480 floats
    ull*   red = (ull*)(sm + 32768 + 20480); // 1024 ull

    const int tid = threadIdx.x;
    const int cid = blockIdx.x;
    const int g   = cid >> 5;              // batch group 0..3
    const int j   = cid & 31;              // N-slice 0..31
    const int B0  = 16 * g;
    const int C0  = 32 * j;

    // --- load Wh slice once ---
    #pragma unroll
    for (int idx = tid; idx < 8192; idx += 256) {
        int k = idx >> 3, q = idx & 7;
        *(float4*)&whs[k * 32 + 4 * q] =
            *(const float4*)&Wh[(size_t)k * HH + C0 + 4 * q];
    }

    // warp-level compute mapping
    const int w    = tid >> 5;
    const int lane = tid & 31;
    const int bh2  = w & 1;                // batch half (8 batches)
    const int ks   = w >> 1;               // k-split 0..3
    const int c16  = lane & 15;            // colpair
    const int bq   = lane >> 4;            // batch quad
    const int bl   = 8 * bh2 + 4 * bq;     // local batch base

    // epilogue mapping
    const int eb = tid & 15;               // local batch
    const int ec = tid >> 4;               // colpair 0..15

    int* flags = &g_flags[g * TT];

    for (int t = 0; t < TT; t++) {
        const int p = t & 1;

        if (t > 0) {
            // wait for all 32 CTAs of this group to publish h_{t-1}
            if (tid == 0) {
                volatile int* f = (volatile int*)&flags[t - 1];
                while (*f < 32) { }
                __threadfence();
            }
            __syncthreads();

            // stage h_{t-1}[group batches][all k] -> hs[k][16]
            const float* src = &g_hT[p ^ 1][0][B0];
            #pragma unroll
            for (int idx = tid; idx < 4096; idx += 256) {
                int k = idx >> 2, q = idx & 3;
                float4 v = __ldcg((const float4*)(src + (size_t)k * BB + 4 * q));
                *(float4*)&hs[k * HSROW + 4 * q] = v;
            }
            __syncthreads();

            // main FMA loop: 256 k per warp, 4 batches x 2 cols per lane
            const float* hp = &hs[(ks * 256) * HSROW + bl];
            const float* wp = &whs[(ks * 256) * 32 + 2 * c16];
            ull a0 = 0ull, a1 = 0ull, a2 = 0ull, a3 = 0ull;
            #pragma unroll 4
            for (int kk = 0; kk < 256; kk++) {
                float4 hv = *(const float4*)hp; hp += HSROW;
                ull wv = *(const ull*)wp;       wp += 32;
                a0 = ffma2(pk2(hv.x, hv.x), wv, a0);
                a1 = ffma2(pk2(hv.y, hv.y), wv, a1);
                a2 = ffma2(pk2(hv.z, hv.z), wv, a2);
                a3 = ffma2(pk2(hv.w, hv.w), wv, a3);
            }
            red[(ks * 16 + bl + 0) * 16 + c16] = a0;
            red[(ks * 16 + bl + 1) * 16 + c16] = a1;
            red[(ks * 16 + bl + 2) * 16 + c16] = a2;
            red[(ks * 16 + bl + 3) * 16 + c16] = a3;
        }
        __syncthreads();

        // epilogue: reduce k-splits, add xp, tanh, publish
        float sx = 0.f, sy = 0.f;
        if (t > 0) {
            #pragma unroll
            for (int s = 0; s < 4; s++) {
                float2 v = upk2(red[(s * 16 + eb) * 16 + ec]);
                sx += v.x; sy += v.y;
            }
        }
        size_t ob = ((size_t)(B0 + eb) * TT + t) * HH + C0 + 2 * ec;
        float2 xp = *(const float2*)&out[ob];
        float rx = tanhf(xp.x + sx);
        float ry = tanhf(xp.y + sy);
        float2 r = make_float2(rx, ry);
        *(float2*)&out[ob] = r;
        g_hT[p][C0 + 2 * ec + 0][B0 + eb] = rx;
        g_hT[p][C0 + 2 * ec + 1][B0 + eb] = ry;

        __threadfence();
        __syncthreads();
        if (tid == 0) atomicAdd(&flags[t], 1);
    }
}

// =====================================================================
// Launch
// =====================================================================
extern "C" void kernel_launch(void* const* d_in, const int* in_sizes, int n_in,
                              void* d_out, int out_size)
{
    const float* x  = nullptr;
    const float* Wx = nullptr;
    const float* Wh = nullptr;
    const float* bv = nullptr;
    for (int i = 0; i < n_in; i++) {
        int s = in_sizes[i];
        if (s == BB * TT * DD)      x  = (const float*)d_in[i];
        else if (s == DD * HH)      Wx = (const float*)d_in[i];
        else if (s == HH * HH)      Wh = (const float*)d_in[i];
        else if (s == HH)           bv = (const float*)d_in[i];
    }
    float* out = (float*)d_out;

    const int smem = (32768 + 20480) * 4 + 1024 * 8;  // 221,184 B
    static int configured = 0;
    if (!configured) {
        cudaFuncSetAttribute(rnn_persist,
                             cudaFuncAttributeMaxDynamicSharedMemorySize, smem);
        configured = 1;
    }

    reset_flags<<<2, 1024>>>();

    dim3 g1((BB * TT) / 64, HH / 64);
    xp_gemm<<<g1, 256>>>(x, Wx, bv, out);

    rnn_persist<<<128, 256, smem>>>(out, Wh);
}

// round 3
// speedup vs baseline: 2.0028x; 1.3970x over previous
#include <cuda_runtime.h>
#include <cuda_bf16.h>
#include <cstddef>

// x[64,512,128] @ Wx[128,1024] + b -> XP (in d_out); then
// h_t = tanh(xp_t + h_{t-1} @ Wh[1024,1024]); out[b,t,:] = h_t.
#define BB 64
#define TT 512
#define DD 128
#define HH 1024

typedef unsigned long long ull;

__device__ __forceinline__ ull pk2(float lo, float hi) {
    ull r; asm("mov.b64 %0, {%1, %2};" : "=l"(r) : "f"(lo), "f"(hi)); return r;
}
__device__ __forceinline__ float2 upk2(ull v) {
    float lo, hi; asm("mov.b64 {%0, %1}, %2;" : "=f"(lo), "=f"(hi) : "l"(v));
    return make_float2(lo, hi);
}
__device__ __forceinline__ ull ffma2(ull a, ull b, ull c) {
    ull d; asm("fma.rn.f32x2 %0, %1, %2, %3;" : "=l"(d) : "l"(a), "l"(b), "l"(c));
    return d;
}

// ---------- global scratch ----------
__device__ float g_h[2][BB][HH];     // h double buffer, row-major [b][k]
__device__ int   g_flags[4 * TT];    // per (batch-group, step) arrival counters

__global__ void reset_flags() {
    int i = blockIdx.x * blockDim.x + threadIdx.x;
    if (i < 4 * TT) g_flags[i] = 0;
}

// =====================================================================
// Kernel 1: XP = x @ Wx + b  -> d_out   (M=32768, K=128, N=1024)
// =====================================================================
__global__ __launch_bounds__(256) void xp_gemm(
    const float* __restrict__ x, const float* __restrict__ Wx,
    const float* __restrict__ bias, float* __restrict__ out)
{
    __shared__ float xs[64 * 68];
    __shared__ float ws[64 * 64];

    const int tid = threadIdx.x;
    const int m0 = blockIdx.x * 64;
    const int n0 = blockIdx.y * 64;
    const int ty = tid >> 4;
    const int tx = tid & 15;

    ull acc01[4] = {0ull, 0ull, 0ull, 0ull};
    ull acc23[4] = {0ull, 0ull, 0ull, 0ull};

    for (int k0 = 0; k0 < DD; k0 += 64) {
        __syncthreads();
        #pragma unroll
        for (int i = tid; i < 1024; i += 256) {
            int r = i >> 4, q = i & 15;
            ((float4*)xs)[r * 17 + q] =
                *(const float4*)&x[(size_t)(m0 + r) * DD + k0 + 4 * q];
        }
        #pragma unroll
        for (int i = tid; i < 1024; i += 256) {
            int r = i >> 4, q = i & 15;
            ((float4*)ws)[i] =
                *(const float4*)&Wx[(size_t)(k0 + r) * HH + n0 + 4 * q];
        }
        __syncthreads();

        #pragma unroll 8
        for (int kk = 0; kk < 64; kk++) {
            ulonglong2 wv = *(const ulonglong2*)&ws[kk * 64 + 4 * tx];
            #pragma unroll
            for (int i = 0; i < 4; i++) {
                float a = xs[(4 * ty + i) * 68 + kk];
                ull aa = pk2(a, a);
                acc01[i] = ffma2(aa, wv.x, acc01[i]);
                acc23[i] = ffma2(aa, wv.y, acc23[i]);
            }
        }
    }

    float4 bv = *(const float4*)&bias[n0 + 4 * tx];
    #pragma unroll
    for (int i = 0; i < 4; i++) {
        float2 p0 = upk2(acc01[i]);
        float2 p1 = upk2(acc23[i]);
        float4 r;
        r.x = p0.x + bv.x; r.y = p0.y + bv.y;
        r.z = p1.x + bv.z; r.w = p1.y + bv.w;
        *(float4*)&out[(size_t)(m0 + 4 * ty + i) * HH + n0 + 4 * tx] = r;
    }
}

// =====================================================================
// Kernel 2: persistent recurrence. 128 CTAs (1/SM), 256 threads.
// CTA (g, j): batches [16g,16g+16), cols [32j,32j+32).
// SMEM (float4 units):
//   wb4[256][33] : Wh slice K-transposed/blocked: wb4[k4][c] =
//                  (W[4k4][C0+c],W[4k4+1][..],W[4k4+2][..],W[4k4+3][..])
//   hb4[256][17] : staged h, hb4[k4][b] = h[B0+b][4k4..4k4+3]
//   red[4][16][32] float : k-split partials
// Pair-over-k f32x2: both operands are natural LDS.128 register pairs.
// =====================================================================
#define WSTR 33
#define HSTR 17

__global__ __launch_bounds__(256) void rnn_persist(
    float* __restrict__ out, const float* __restrict__ Wh)
{
    extern __shared__ float4 sm4[];
    float4* wb4 = sm4;                         // 8448 float4
    float4* hb4 = sm4 + 256 * WSTR;            // 4352 float4
    float*  red = (float*)(sm4 + 256 * WSTR + 256 * HSTR); // 2048 floats

    const int tid = threadIdx.x;
    const int cid = blockIdx.x;
    const int g   = cid >> 5;               // batch group 0..3
    const int j   = cid & 31;               // N-slice 0..31
    const int B0  = 16 * g;
    const int C0  = 32 * j;

    // --- one-time: load Wh slice, transposing K into float4 blocks ---
    for (int idx = tid; idx < 8192; idx += 256) {
        int k4 = idx >> 5, c = idx & 31;
        const float* p = &Wh[(size_t)(4 * k4) * HH + C0 + c];
        float4 v;
        v.x = p[0]; v.y = p[HH]; v.z = p[2 * HH]; v.w = p[3 * HH];
        wb4[k4 * WSTR + c] = v;
    }

    // compute mapping: warp -> (k-split, batch-half); lane -> (colpair, batch-quad)
    const int w    = tid >> 5;
    const int lane = tid & 31;
    const int ks   = w >> 1;                // 0..3 : k4 in [64ks, 64ks+64)
    const int bh2  = w & 1;
    const int c16  = lane & 15;             // cols 2*c16, 2*c16+1
    const int bq   = lane >> 4;
    const int bl   = 8 * bh2 + 4 * bq;      // local batches bl..bl+3

    // epilogue mapping: thread -> (batch, colpair), coalesced in c
    const int eb = tid >> 4;                // 0..15
    const int ec = tid & 15;                // cols 2*ec, 2*ec+1

    int* flags = &g_flags[g * TT];

    for (int t = 0; t < TT; t++) {
        const int p = t & 1;

        // prefetch xp (independent of h_{t-1})
        size_t ob = ((size_t)(B0 + eb) * TT + t) * HH + C0 + 2 * ec;
        float2 xp = __ldcg((const float2*)&out[ob]);

        if (t > 0) {
            if (tid == 0) {
                volatile int* f = (volatile int*)&flags[t - 1];
                while (*f < 32) { }
                __threadfence();
            }
            __syncthreads();

            // stage h_{t-1}: coalesced gmem read, bank-spread smem write
            const float4* src = (const float4*)&g_h[p ^ 1][B0][0];
            #pragma unroll
            for (int i = 0; i < 16; i++) {
                int idx = i * 256 + tid;
                int b = idx >> 8, k4 = idx & 255;
                hb4[k4 * HSTR + b] = __ldcg(src + b * 256 + k4);
            }
            __syncthreads();

            // main loop: per kk, 6 LDS.128 + 16 ffma2, zero packing movs
            const float4* hp = hb4 + (ks * 64) * HSTR + bl;
            const float4* wp = wb4 + (ks * 64) * WSTR + 2 * c16;
            ull a00 = 0, a01 = 0, a10 = 0, a11 = 0;
            ull a20 = 0, a21 = 0, a30 = 0, a31 = 0;
            #pragma unroll 4
            for (int kk = 0; kk < 64; kk++) {
                ulonglong2 wc0 = *(const ulonglong2*)(wp);
                ulonglong2 wc1 = *(const ulonglong2*)(wp + 1);
                ulonglong2 h0  = *(const ulonglong2*)(hp + 0);
                ulonglong2 h1  = *(const ulonglong2*)(hp + 1);
                ulonglong2 h2  = *(const ulonglong2*)(hp + 2);
                ulonglong2 h3  = *(const ulonglong2*)(hp + 3);
                a00 = ffma2(h0.x, wc0.x, a00); a00 = ffma2(h0.y, wc0.y, a00);
                a01 = ffma2(h0.x, wc1.x, a01); a01 = ffma2(h0.y, wc1.y, a01);
                a10 = ffma2(h1.x, wc0.x, a10); a10 = ffma2(h1.y, wc0.y, a10);
                a11 = ffma2(h1.x, wc1.x, a11); a11 = ffma2(h1.y, wc1.y, a11);
                a20 = ffma2(h2.x, wc0.x, a20); a20 = ffma2(h2.y, wc0.y, a20);
                a21 = ffma2(h2.x, wc1.x, a21); a21 = ffma2(h2.y, wc1.y, a21);
                a30 = ffma2(h3.x, wc0.x, a30); a30 = ffma2(h3.y, wc0.y, a30);
                a31 = ffma2(h3.x, wc1.x, a31); a31 = ffma2(h3.y, wc1.y, a31);
                hp += HSTR; wp += WSTR;
            }
            // horizontal add (even-k + odd-k halves) -> red
            float2 v;
            int rb = ks * 16;
            v = upk2(a00); red[(rb + bl + 0) * 32 + 2 * c16 + 0] = v.x + v.y;
            v = upk2(a01); red[(rb + bl + 0) * 32 + 2 * c16 + 1] = v.x + v.y;
            v = upk2(a10); red[(rb + bl + 1) * 32 + 2 * c16 + 0] = v.x + v.y;
            v = upk2(a11); red[(rb + bl + 1) * 32 + 2 * c16 + 1] = v.x + v.y;
            v = upk2(a20); red[(rb + bl + 2) * 32 + 2 * c16 + 0] = v.x + v.y;
            v = upk2(a21); red[(rb + bl + 2) * 32 + 2 * c16 + 1] = v.x + v.y;
            v = upk2(a30); red[(rb + bl + 3) * 32 + 2 * c16 + 0] = v.x + v.y;
            v = upk2(a31); red[(rb + bl + 3) * 32 + 2 * c16 + 1] = v.x + v.y;
        }
        __syncthreads();

        // epilogue: reduce k-splits, add xp, tanh, publish
        float sx = xp.x, sy = xp.y;
        if (t > 0) {
            #pragma unroll
            for (int s = 0; s < 4; s++) {
                float2 rv = *(const float2*)&red[(s * 16 + eb) * 32 + 2 * ec];
                sx += rv.x; sy += rv.y;
            }
        }
        float rx = tanhf(sx), ry = tanhf(sy);
        *(float2*)&out[ob] = make_float2(rx, ry);
        *(float2*)&g_h[p][B0 + eb][C0 + 2 * ec] = make_float2(rx, ry);

        __syncthreads();
        if (tid == 0) {
            __threadfence();
            atomicAdd(&flags[t], 1);
        }
    }
}

// =====================================================================
// Launch
// =====================================================================
extern "C" void kernel_launch(void* const* d_in, const int* in_sizes, int n_in,
                              void* d_out, int out_size)
{
    const float* x  = nullptr;
    const float* Wx = nullptr;
    const float* Wh = nullptr;
    const float* bv = nullptr;
    for (int i = 0; i < n_in; i++) {
        int s = in_sizes[i];
        if (s == BB * TT * DD)      x  = (const float*)d_in[i];
        else if (s == DD * HH)      Wx = (const float*)d_in[i];
        else if (s == HH * HH)      Wh = (const float*)d_in[i];
        else if (s == HH)           bv = (const float*)d_in[i];
    }
    float* out = (float*)d_out;

    const int smem = (256 * WSTR + 256 * HSTR) * 16 + 2048 * 4; // 212,992 B
    static int configured = 0;
    if (!configured) {
        cudaFuncSetAttribute(rnn_persist,
                             cudaFuncAttributeMaxDynamicSharedMemorySize, smem);
        configured = 1;
    }

    reset_flags<<<2, 1024>>>();

    dim3 g1((BB * TT) / 64, HH / 64);
    xp_gemm<<<g1, 256>>>(x, Wx, bv, out);

    rnn_persist<<<128, 256, smem>>>(out, Wh);
}

// round 4
// speedup vs baseline: 3.0549x; 1.5253x over previous
#include <cuda_runtime.h>
#include <cuda_bf16.h>
#include <cstddef>

// x[64,512,128] @ Wx[128,1024] + b -> XP (in d_out); then
// h_t = tanh(xp_t + h_{t-1} @ Wh[1024,1024]); out[b,t,:] = h_t.
#define BB 64
#define TT 512
#define DD 128
#define HH 1024

typedef unsigned long long ull;

__device__ __forceinline__ ull pk2(float lo, float hi) {
    ull r; asm("mov.b64 %0, {%1, %2};" : "=l"(r) : "f"(lo), "f"(hi)); return r;
}
__device__ __forceinline__ float2 upk2(ull v) {
    float lo, hi; asm("mov.b64 {%0, %1}, %2;" : "=f"(lo), "=f"(hi) : "l"(v));
    return make_float2(lo, hi);
}
__device__ __forceinline__ ull ffma2(ull a, ull b, ull c) {
    ull d; asm("fma.rn.f32x2 %0, %1, %2, %3;" : "=l"(d) : "l"(a), "l"(b), "l"(c));
    return d;
}
__device__ __forceinline__ int ld_acq(const int* p) {
    int v; asm volatile("ld.acquire.gpu.global.s32 %0, [%1];" : "=r"(v) : "l"(p));
    return v;
}
__device__ __forceinline__ void red_rel_add1(int* p) {
    asm volatile("red.release.gpu.global.add.s32 [%0], 1;" :: "l"(p) : "memory");
}

// ---------- global scratch ----------
__device__ float g_h[2][BB][HH];     // h double buffer, row-major [b][k]
__device__ int   g_flags[4 * TT];    // per (batch-group, step) warp-arrival counters

// =====================================================================
// Kernel 1: XP = x @ Wx + b  -> d_out   (M=32768, K=128, N=1024)
// Block (0,0) also resets the step flags (runs before rnn_persist).
// =====================================================================
__global__ __launch_bounds__(256) void xp_gemm(
    const float* __restrict__ x, const float* __restrict__ Wx,
    const float* __restrict__ bias, float* __restrict__ out)
{
    __shared__ float xs[64 * 68];
    __shared__ float ws[64 * 64];

    const int tid = threadIdx.x;
    if (blockIdx.x == 0 && blockIdx.y == 0) {
        #pragma unroll
        for (int i = tid; i < 4 * TT; i += 256) g_flags[i] = 0;
    }

    const int m0 = blockIdx.x * 64;
    const int n0 = blockIdx.y * 64;
    const int ty = tid >> 4;
    const int tx = tid & 15;

    ull acc01[4] = {0ull, 0ull, 0ull, 0ull};
    ull acc23[4] = {0ull, 0ull, 0ull, 0ull};

    for (int k0 = 0; k0 < DD; k0 += 64) {
        __syncthreads();
        #pragma unroll
        for (int i = tid; i < 1024; i += 256) {
            int r = i >> 4, q = i & 15;
            ((float4*)xs)[r * 17 + q] =
                *(const float4*)&x[(size_t)(m0 + r) * DD + k0 + 4 * q];
        }
        #pragma unroll
        for (int i = tid; i < 1024; i += 256) {
            int r = i >> 4, q = i & 15;
            ((float4*)ws)[i] =
                *(const float4*)&Wx[(size_t)(k0 + r) * HH + n0 + 4 * q];
        }
        __syncthreads();

        #pragma unroll 8
        for (int kk = 0; kk < 64; kk++) {
            ulonglong2 wv = *(const ulonglong2*)&ws[kk * 64 + 4 * tx];
            #pragma unroll
            for (int i = 0; i < 4; i++) {
                float a = xs[(4 * ty + i) * 68 + kk];
                ull aa = pk2(a, a);
                acc01[i] = ffma2(aa, wv.x, acc01[i]);
                acc23[i] = ffma2(aa, wv.y, acc23[i]);
            }
        }
    }

    float4 bv = *(const float4*)&bias[n0 + 4 * tx];
    #pragma unroll
    for (int i = 0; i < 4; i++) {
        float2 p0 = upk2(acc01[i]);
        float2 p1 = upk2(acc23[i]);
        float4 r;
        r.x = p0.x + bv.x; r.y = p0.y + bv.y;
        r.z = p1.x + bv.z; r.w = p1.y + bv.w;
        *(float4*)&out[(size_t)(m0 + 4 * ty + i) * HH + n0 + 4 * tx] = r;
    }
}

// =====================================================================
// Kernel 2: persistent recurrence. 128 CTAs (1/SM), 256 threads (8 warps).
// CTA (g, j): batches [16g,16g+16), cols [32j,32j+32).
// Warp w = k-chunk ks: k in [128ks, 128ks+128); lane (cq=lane&7, bq=lane>>3)
// computes batches 4bq..4bq+3  x  cols 4cq..4cq+3 (16 packed-over-k accs).
// SMEM (float4):
//   wb4[256][33] : Wh K-blocked, col c at slot (c&3)*8+(c>>2)  (1-wf LDS)
//   hb4[256][17] : staged h,  batch b at slot (b&3)*4+(b>>2)   (1-wf LDS)
//   red[8][16][32] float : k-split partials
// Per-warp acquire-poll / release-add flags (target 32 CTAs x 8 warps).
// =====================================================================
#define WSTR 33
#define HSTR 17

__global__ __launch_bounds__(256) void rnn_persist(
    float* __restrict__ out, const float* __restrict__ Wh)
{
    extern __shared__ float4 sm4[];
    float4* wb4 = sm4;                              // 8448 float4
    float4* hb4 = sm4 + 256 * WSTR;                 // 4352 float4
    float*  red = (float*)(sm4 + 256 * WSTR + 256 * HSTR); // 4096 floats

    const int tid = threadIdx.x;
    const int g   = blockIdx.x >> 5;
    const int j   = blockIdx.x & 31;
    const int B0  = 16 * g;
    const int C0  = 32 * j;

    // one-time: Wh slice, K-transposed into float4 blocks, permuted col slots
    for (int idx = tid; idx < 8192; idx += 256) {
        int k4 = idx >> 5, c = idx & 31;
        const float* p = &Wh[(size_t)(4 * k4) * HH + C0 + c];
        float4 v;
        v.x = p[0]; v.y = p[HH]; v.z = p[2 * HH]; v.w = p[3 * HH];
        wb4[k4 * WSTR + ((c & 3) * 8 + (c >> 2))] = v;
    }
    // (visibility of wb4 to all warps is established by the t=0 __syncthreads)

    const int ks   = tid >> 5;          // warp = k-chunk 0..7
    const int lane = tid & 31;
    const int cq   = lane & 7;          // cols 4cq..4cq+3
    const int bq   = lane >> 3;         // batches 4bq..4bq+3

    const int eb = tid >> 4;            // epilogue batch 0..15
    const int ec = tid & 15;            // epilogue colpair -> cols 2ec,2ec+1

    int* flag = &g_flags[g * TT];

    for (int t = 0; t < TT; t++) {
        const int p = t & 1;

        // prefetch xp for this step (independent of h_{t-1})
        size_t ob = ((size_t)(B0 + eb) * TT + t) * HH + C0 + 2 * ec;
        float2 xp = __ldcg((const float2*)&out[ob]);

        if (t > 0) {
            // acquire-poll: wait for all 256 producer warps of this group
            while (ld_acq(&flag[t - 1]) < 256) { }

            // stage this warp's own 128-k chunk of h_{t-1} (L1-bypassed)
            const float4* src = (const float4*)&g_h[p ^ 1][B0][0]; // [16][256]
            const int k4r = 32 * ks + lane;
            #pragma unroll
            for (int b = 0; b < 16; b++) {
                float4 v = __ldcg(src + b * 256 + k4r);
                hb4[k4r * HSTR + ((b & 3) * 4 + (b >> 2))] = v;
            }
            __syncwarp();

            // compute: 32 k4 iters; per iter 8 one-wavefront LDS.128 + 32 ffma2
            const float4* hp = hb4 + (32 * ks) * HSTR + bq;
            const float4* wp = wb4 + (32 * ks) * WSTR + cq;
            ull a[4][4];
            #pragma unroll
            for (int bi = 0; bi < 4; bi++)
                #pragma unroll
                for (int ci = 0; ci < 4; ci++) a[bi][ci] = 0ull;

            #pragma unroll 2
            for (int kk = 0; kk < 32; kk++) {
                ulonglong2 wv[4], hv[4];
                #pragma unroll
                for (int i = 0; i < 4; i++)
                    wv[i] = *(const ulonglong2*)(wp + 8 * i);
                #pragma unroll
                for (int i = 0; i < 4; i++)
                    hv[i] = *(const ulonglong2*)(hp + 4 * i);
                #pragma unroll
                for (int bi = 0; bi < 4; bi++) {
                    #pragma unroll
                    for (int ci = 0; ci < 4; ci++) {
                        a[bi][ci] = ffma2(hv[bi].x, wv[ci].x, a[bi][ci]);
                        a[bi][ci] = ffma2(hv[bi].y, wv[ci].y, a[bi][ci]);
                    }
                }
                hp += HSTR; wp += WSTR;
            }

            // horizontal add (even/odd k halves) -> red[ks][b][c]
            #pragma unroll
            for (int bi = 0; bi < 4; bi++) {
                float2 v0 = upk2(a[bi][0]);
                float2 v1 = upk2(a[bi][1]);
                float2 v2 = upk2(a[bi][2]);
                float2 v3 = upk2(a[bi][3]);
                float4 r4;
                r4.x = v0.x + v0.y; r4.y = v1.x + v1.y;
                r4.z = v2.x + v2.y; r4.w = v3.x + v3.y;
                *(float4*)&red[(ks * 16 + 4 * bq + bi) * 32 + 4 * cq] = r4;
            }
        }
        __syncthreads();

        // epilogue: reduce 8 k-splits, add xp, tanh, publish h
        float sx = xp.x, sy = xp.y;
        if (t > 0) {
            #pragma unroll
            for (int s = 0; s < 8; s++) {
                float2 rv = *(const float2*)&red[(s * 16 + eb) * 32 + 2 * ec];
                sx += rv.x; sy += rv.y;
            }
        }
        float rx = tanhf(sx), ry = tanhf(sy);
        *(float2*)&g_h[p][B0 + eb][C0 + 2 * ec] = make_float2(rx, ry);
        __syncwarp();
        if (lane == 0) red_rel_add1(&flag[t]);   // release covers warp's stores
        *(float2*)&out[ob] = make_float2(rx, ry); // off critical path
    }
}

// =====================================================================
// Launch
// =====================================================================
extern "C" void kernel_launch(void* const* d_in, const int* in_sizes, int n_in,
                              void* d_out, int out_size)
{
    const float* x  = nullptr;
    const float* Wx = nullptr;
    const float* Wh = nullptr;
    const float* bv = nullptr;
    for (int i = 0; i < n_in; i++) {
        int s = in_sizes[i];
        if (s == BB * TT * DD)      x  = (const float*)d_in[i];
        else if (s == DD * HH)      Wx = (const float*)d_in[i];
        else if (s == HH * HH)      Wh = (const float*)d_in[i];
        else if (s == HH)           bv = (const float*)d_in[i];
    }
    float* out = (float*)d_out;

    const int smem = (256 * WSTR + 256 * HSTR) * 16 + 4096 * 4; // 221,184 B
    static int configured = 0;
    if (!configured) {
        cudaFuncSetAttribute(rnn_persist,
                             cudaFuncAttributeMaxDynamicSharedMemorySize, smem);
        configured = 1;
    }

    dim3 g1((BB * TT) / 64, HH / 64);
    xp_gemm<<<g1, 256>>>(x, Wx, bv, out);

    rnn_persist<<<128, 256, smem>>>(out, Wh);
}

// round 5
// speedup vs baseline: 3.1125x; 1.0188x over previous
#include <cuda_runtime.h>
#include <cuda_bf16.h>
#include <cstddef>

// x[64,512,128] @ Wx[128,1024] + b -> XP (in d_out); then
// h_t = tanh(xp_t + h_{t-1} @ Wh[1024,1024]); out[b,t,:] = h_t.
#define BB 64
#define TT 512
#define DD 128
#define HH 1024

typedef unsigned long long ull;

__device__ __forceinline__ ull pk2(float lo, float hi) {
    ull r; asm("mov.b64 %0, {%1, %2};" : "=l"(r) : "f"(lo), "f"(hi)); return r;
}
__device__ __forceinline__ float2 upk2(ull v) {
    float lo, hi; asm("mov.b64 {%0, %1}, %2;" : "=f"(lo), "=f"(hi) : "l"(v));
    return make_float2(lo, hi);
}
__device__ __forceinline__ ull ffma2(ull a, ull b, ull c) {
    ull d; asm("fma.rn.f32x2 %0, %1, %2, %3;" : "=l"(d) : "l"(a), "l"(b), "l"(c));
    return d;
}
__device__ __forceinline__ int ld_acq(const int* p) {
    int v; asm volatile("ld.acquire.gpu.global.s32 %0, [%1];" : "=r"(v) : "l"(p));
    return v;
}
__device__ __forceinline__ void red_rel_add1(int* p) {
    asm volatile("red.release.gpu.global.add.s32 [%0], 1;" :: "l"(p) : "memory");
}
// fast tanh: exp-based, ~1e-6 rel err (budget 1e-3); clamp avoids inf/inf.
__device__ __forceinline__ float fast_tanh(float x) {
    x = fminf(fmaxf(x, -15.f), 15.f);
    float e = __expf(x + x);
    return __fdividef(e - 1.f, e + 1.f);
}

// ---------- global scratch ----------
__device__ float g_h[2][BB][HH];         // h double buffer, row-major [b][k]
__device__ int   g_flags[4][TT][8];      // per (group, step, k-chunk) warp arrivals

// =====================================================================
// Kernel 1: XP = x @ Wx + b  -> d_out   (M=32768, K=128, N=1024)
// Block (0,0) also resets the step flags (runs before rnn_persist).
// =====================================================================
__global__ __launch_bounds__(256) void xp_gemm(
    const float* __restrict__ x, const float* __restrict__ Wx,
    const float* __restrict__ bias, float* __restrict__ out)
{
    __shared__ float xs[64 * 68];
    __shared__ float ws[64 * 64];

    const int tid = threadIdx.x;
    if (blockIdx.x == 0 && blockIdx.y == 0) {
        int* f = &g_flags[0][0][0];
        #pragma unroll
        for (int i = tid; i < 4 * TT * 8; i += 256) f[i] = 0;
    }

    const int m0 = blockIdx.x * 64;
    const int n0 = blockIdx.y * 64;
    const int ty = tid >> 4;
    const int tx = tid & 15;

    ull acc01[4] = {0ull, 0ull, 0ull, 0ull};
    ull acc23[4] = {0ull, 0ull, 0ull, 0ull};

    for (int k0 = 0; k0 < DD; k0 += 64) {
        __syncthreads();
        #pragma unroll
        for (int i = tid; i < 1024; i += 256) {
            int r = i >> 4, q = i & 15;
            ((float4*)xs)[r * 17 + q] =
                *(const float4*)&x[(size_t)(m0 + r) * DD + k0 + 4 * q];
        }
        #pragma unroll
        for (int i = tid; i < 1024; i += 256) {
            int r = i >> 4, q = i & 15;
            ((float4*)ws)[i] =
                *(const float4*)&Wx[(size_t)(k0 + r) * HH + n0 + 4 * q];
        }
        __syncthreads();

        #pragma unroll 8
        for (int kk = 0; kk < 64; kk++) {
            ulonglong2 wv = *(const ulonglong2*)&ws[kk * 64 + 4 * tx];
            #pragma unroll
            for (int i = 0; i < 4; i++) {
                float a = xs[(4 * ty + i) * 68 + kk];
                ull aa = pk2(a, a);
                acc01[i] = ffma2(aa, wv.x, acc01[i]);
                acc23[i] = ffma2(aa, wv.y, acc23[i]);
            }
        }
    }

    float4 bv = *(const float4*)&bias[n0 + 4 * tx];
    #pragma unroll
    for (int i = 0; i < 4; i++) {
        float2 p0 = upk2(acc01[i]);
        float2 p1 = upk2(acc23[i]);
        float4 r;
        r.x = p0.x + bv.x; r.y = p0.y + bv.y;
        r.z = p1.x + bv.z; r.w = p1.y + bv.w;
        *(float4*)&out[(size_t)(m0 + 4 * ty + i) * HH + n0 + 4 * tx] = r;
    }
}

// =====================================================================
// Kernel 2: persistent recurrence. 128 CTAs (1/SM), 256 threads (8 warps).
// CTA (g, j): batches [16g,16g+16), cols [32j,32j+32); produces k-chunk j>>2.
// Warp ks consumes k-chunk ks: polls flag[g][t-1][ks] (4 producer CTAs x 8
// warps = 32), stages its own 128-k slice of h, computes 16x32 tile partials.
// SMEM (float4):
//   wb4[256][33] : Wh K-blocked, col c at slot (c&3)*8+(c>>2)  (1-wf LDS)
//   hb4[256][17] : staged h,  batch b at slot (b&3)*4+(b>>2)   (1-wf LDS)
//   red[8][16][32] float : k-split partials
// =====================================================================
#define WSTR 33
#define HSTR 17

__global__ __launch_bounds__(256) void rnn_persist(
    float* __restrict__ out, const float* __restrict__ Wh)
{
    extern __shared__ float4 sm4[];
    float4* wb4 = sm4;                              // 8448 float4
    float4* hb4 = sm4 + 256 * WSTR;                 // 4352 float4
    float*  red = (float*)(sm4 + 256 * WSTR + 256 * HSTR); // 4096 floats

    const int tid = threadIdx.x;
    const int g   = blockIdx.x >> 5;
    const int j   = blockIdx.x & 31;
    const int B0  = 16 * g;
    const int C0  = 32 * j;
    const int jc  = j >> 2;             // chunk this CTA produces

    // one-time: Wh slice, K-transposed into float4 blocks, permuted col slots
    for (int idx = tid; idx < 8192; idx += 256) {
        int k4 = idx >> 5, c = idx & 31;
        const float* p = &Wh[(size_t)(4 * k4) * HH + C0 + c];
        float4 v;
        v.x = p[0]; v.y = p[HH]; v.z = p[2 * HH]; v.w = p[3 * HH];
        wb4[k4 * WSTR + ((c & 3) * 8 + (c >> 2))] = v;
    }
    __syncthreads();   // wb4 visible to all warps before t=0 epilogue path

    const int ks   = tid >> 5;          // warp = consumed k-chunk 0..7
    const int lane = tid & 31;
    const int cq   = lane & 7;          // cols 4cq..4cq+3
    const int bq   = lane >> 3;         // batches 4bq..4bq+3

    const int eb = tid >> 4;            // epilogue batch 0..15
    const int ec = tid & 15;            // epilogue colpair -> cols 2ec,2ec+1

    for (int t = 0; t < TT; t++) {
        const int p = t & 1;

        // prefetch xp for this step (independent of h_{t-1})
        size_t ob = ((size_t)(B0 + eb) * TT + t) * HH + C0 + 2 * ec;
        float2 xp = __ldcg((const float2*)&out[ob]);

        if (t > 0) {
            // wait only for this chunk's 4 producer CTAs (32 warps)
            int* myflag = &g_flags[g][t - 1][ks];
            while (ld_acq(myflag) < 32) { }

            // stage this warp's own 128-k chunk of h_{t-1} (L1-bypassed)
            const float4* src = (const float4*)&g_h[p ^ 1][B0][0]; // [16][256]
            const int k4r = 32 * ks + lane;
            #pragma unroll
            for (int b = 0; b < 16; b++) {
                float4 v = __ldcg(src + b * 256 + k4r);
                hb4[k4r * HSTR + ((b & 3) * 4 + (b >> 2))] = v;
            }
            __syncwarp();

            // compute: 32 k4 iters; per iter 8 one-wavefront LDS.128 + 32 ffma2
            const float4* hp = hb4 + (32 * ks) * HSTR + bq;
            const float4* wp = wb4 + (32 * ks) * WSTR + cq;
            ull a[4][4];
            #pragma unroll
            for (int bi = 0; bi < 4; bi++)
                #pragma unroll
                for (int ci = 0; ci < 4; ci++) a[bi][ci] = 0ull;

            #pragma unroll 2
            for (int kk = 0; kk < 32; kk++) {
                ulonglong2 wv[4], hv[4];
                #pragma unroll
                for (int i = 0; i < 4; i++)
                    wv[i] = *(const ulonglong2*)(wp + 8 * i);
                #pragma unroll
                for (int i = 0; i < 4; i++)
                    hv[i] = *(const ulonglong2*)(hp + 4 * i);
                #pragma unroll
                for (int bi = 0; bi < 4; bi++) {
                    #pragma unroll
                    for (int ci = 0; ci < 4; ci++) {
                        a[bi][ci] = ffma2(hv[bi].x, wv[ci].x, a[bi][ci]);
                        a[bi][ci] = ffma2(hv[bi].y, wv[ci].y, a[bi][ci]);
                    }
                }
                hp += HSTR; wp += WSTR;
            }

            // horizontal add (even/odd k halves) -> red[ks][b][c]
            #pragma unroll
            for (int bi = 0; bi < 4; bi++) {
                float2 v0 = upk2(a[bi][0]);
                float2 v1 = upk2(a[bi][1]);
                float2 v2 = upk2(a[bi][2]);
                float2 v3 = upk2(a[bi][3]);
                float4 r4;
                r4.x = v0.x + v0.y; r4.y = v1.x + v1.y;
                r4.z = v2.x + v2.y; r4.w = v3.x + v3.y;
                *(float4*)&red[(ks * 16 + 4 * bq + bi) * 32 + 4 * cq] = r4;
            }
        }
        __syncthreads();

        // epilogue: reduce 8 k-splits, add xp, tanh, publish h
        float sx = xp.x, sy = xp.y;
        if (t > 0) {
            #pragma unroll
            for (int s = 0; s < 8; s++) {
                float2 rv = *(const float2*)&red[(s * 16 + eb) * 32 + 2 * ec];
                sx += rv.x; sy += rv.y;
            }
        }
        float rx = fast_tanh(sx), ry = fast_tanh(sy);
        *(float2*)&g_h[p][B0 + eb][C0 + 2 * ec] = make_float2(rx, ry);
        __syncwarp();
        if (lane == 0) red_rel_add1(&g_flags[g][t][jc]); // release covers stores
        *(float2*)&out[ob] = make_float2(rx, ry);        // off critical path

        // red reuse hazard fence (per-chunk flags no longer order it):
        __syncthreads();
    }
}

// =====================================================================
// Launch
// =====================================================================
extern "C" void kernel_launch(void* const* d_in, const int* in_sizes, int n_in,
                              void* d_out, int out_size)
{
    const float* x  = nullptr;
    const float* Wx = nullptr;
    const float* Wh = nullptr;
    const float* bv = nullptr;
    for (int i = 0; i < n_in; i++) {
        int s = in_sizes[i];
        if (s == BB * TT * DD)      x  = (const float*)d_in[i];
        else if (s == DD * HH)      Wx = (const float*)d_in[i];
        else if (s == HH * HH)      Wh = (const float*)d_in[i];
        else if (s == HH)           bv = (const float*)d_in[i];
    }
    float* out = (float*)d_out;

    const int smem = (256 * WSTR + 256 * HSTR) * 16 + 4096 * 4; // 221,184 B
    static int configured = 0;
    if (!configured) {
        cudaFuncSetAttribute(rnn_persist,
                             cudaFuncAttributeMaxDynamicSharedMemorySize, smem);
        configured = 1;
    }

    dim3 g1((BB * TT) / 64, HH / 64);
    xp_gemm<<<g1, 256>>>(x, Wx, bv, out);

    rnn_persist<<<128, 256, smem>>>(out, Wh);
}